// round 12
// baseline (speedup 1.0000x reference)
#include <cuda_runtime.h>
#include <cuda_bf16.h>

// ValScores: per-class mean of preds rows (segment reduction by label) + EMA.
//   out[c,:] = cnt[c]>0 ? 0.1*mean_c(preds) + 0.9*val_preds[c,:] : val_preds[c,:]
//
// Structure lessons (R2..R11): whole contiguous 4000B rows per CTA; 32 regs /
// 8 CTAs/SM pinned; no spin barriers / tickets / partial-exchange. R11 ncu
// showed scatter was LATENCY-bound (int4 form -> only 128 CTAs, occ 11%,
// 6.4us), not contention-bound.
//
// This round (2 launches):
//   k_scatter_init : 1 element/thread scatter (grid=512 CTAs -> 27 warps/SM
//                    hides ATOMG ~318cyc) FUSED with out = 0.9*val_preds
//                    init (independent work, overlaps under the atomics).
//   k_partial      : grid=2*C, pinned (256,8). CTA (2c+h) sums half of class
//                    c's whole rows (proven hot loop), scales by 0.1/cnt,
//                    fire-and-forget float atomicAdd into out. Empty class:
//                    h=0 CTA overwrites with val_preds (stream-ordered after
//                    init). Second arriver resets cursors -> zero state per
//                    graph replay.

#define C_MAX   1024
#define KSUB    16
#define CAP     128            // per sub-list capacity (expected ~8 +- 3)
#define SMAX    (KSUB * CAP)   // 2048 indices, 8KB smem
#define GAMMA   0.9f
#define ONE_MINUS_GAMMA 0.1f

__device__ int g_cursor[C_MAX * KSUB];        // zero-init at module load
__device__ int g_rowidx[C_MAX * KSUB * CAP];  // 8 MB scratch
__device__ int g_rank[C_MAX];                 // zero-init arrival counters

// ---------------------------------------------------------------------------
// Fused scatter + output init. grid = 512 CTAs x 256 threads.
// Scatter: 1 element/thread (max latency hiding). Init: out = GAMMA*val_preds
// (grid-stride float4) — independent of counts; empty classes corrected later.
// ---------------------------------------------------------------------------
__global__ __launch_bounds__(256) void k_scatter_init(
    const int*   __restrict__ labels,
    const float* __restrict__ val_preds,
    float*       __restrict__ out,
    int N, int tot4)
{
    int gid = blockIdx.x * 256 + threadIdx.x;
    int nth = gridDim.x * 256;

    // Scatter: coalesced label load, one independent atomic per thread.
    for (int i = gid; i < N; i += nth) {
        int b = labels[i] * KSUB + (i & (KSUB - 1));
        int p = atomicAdd(&g_cursor[b], 1);
        if (p < CAP) g_rowidx[b * CAP + p] = i;
    }

    // Init: out = GAMMA * val_preds (vectorized; overlaps the atomics).
    const float4* vp4 = (const float4*)val_preds;
    float4*       o4  = (float4*)out;
    for (int i = gid; i < tot4; i += nth) {
        float4 v = vp4[i];
        o4[i] = make_float4(GAMMA * v.x, GAMMA * v.y, GAMMA * v.z, GAMMA * v.w);
    }
}

// ---------------------------------------------------------------------------
// Partial reduce: grid = 2*C, 256 threads, pinned 8 CTAs/SM. CTA (2c+h) sums
// half of class c's rows (whole contiguous rows), scales, REDG-adds into out.
// ---------------------------------------------------------------------------
__global__ __launch_bounds__(256, 8) void k_partial_v4(
    const float* __restrict__ preds,
    const float* __restrict__ val_preds,
    float* __restrict__ out,
    int C)
{
    int c    = blockIdx.x >> 1;
    int h    = blockIdx.x & 1;
    int tid  = threadIdx.x;

    __shared__ int s_base[KSUB + 1];
    __shared__ int s_idx[SMAX];

    // Per-sub counts -> prefix (thread 0; KSUB independent loads).
    if (tid == 0) {
        int tot = 0;
        #pragma unroll
        for (int s = 0; s < KSUB; ++s) {
            s_base[s] = tot;
            int cs = g_cursor[c * KSUB + s];
            tot += (cs < CAP ? cs : CAP);
        }
        s_base[KSUB] = tot;
    }
    __syncthreads();

    // Stage full compacted index list into smem.
    #pragma unroll
    for (int s = 0; s < KSUB; ++s) {
        int lo = s_base[s], cs = s_base[s + 1] - lo;
        const int* src = &g_rowidx[(c * KSUB + s) * CAP];
        for (int j = tid; j < cs; j += 256) s_idx[lo + j] = src[j];
    }
    __syncthreads();

    // Second arriver resets this class's cursors + rank (both have latched).
    __shared__ int s_rank;
    if (tid == 0) s_rank = atomicAdd(&g_rank[c], 1);
    __syncthreads();
    if (s_rank == 1) {
        if (tid < KSUB) g_cursor[c * KSUB + tid] = 0;
        if (tid == 0)   g_rank[c] = 0;
    }

    int cnt  = s_base[KSUB];
    int col4 = tid * 4;
    if (col4 >= C) return;

    if (cnt == 0) {
        // Correct init's 0.9*val back to val (h=0 only; ordered after init).
        if (h == 0) {
            float4 vp = *(const float4*)(val_preds + (size_t)c * C + col4);
            *(float4*)(out + (size_t)c * C + col4) = vp;
        }
        return;
    }

    int lo = h ? (cnt >> 1) : 0;
    int hi = h ? cnt        : (cnt >> 1);

    float ax = 0.f, ay = 0.f, az = 0.f, aw = 0.f;
    int r = lo;
    // 4 independent 16B streaming loads in flight (32-reg MLP/occupancy max).
    for (; r + 3 < hi; r += 4) {
        const float4* p0 = (const float4*)(preds + (size_t)s_idx[r + 0] * C + col4);
        const float4* p1 = (const float4*)(preds + (size_t)s_idx[r + 1] * C + col4);
        const float4* p2 = (const float4*)(preds + (size_t)s_idx[r + 2] * C + col4);
        const float4* p3 = (const float4*)(preds + (size_t)s_idx[r + 3] * C + col4);
        float4 v0 = __ldcs(p0);
        float4 v1 = __ldcs(p1);
        float4 v2 = __ldcs(p2);
        float4 v3 = __ldcs(p3);
        ax += v0.x; ay += v0.y; az += v0.z; aw += v0.w;
        ax += v1.x; ay += v1.y; az += v1.z; aw += v1.w;
        ax += v2.x; ay += v2.y; az += v2.z; aw += v2.w;
        ax += v3.x; ay += v3.y; az += v3.z; aw += v3.w;
    }
    for (; r < hi; ++r) {
        float4 v = __ldcs((const float4*)(preds + (size_t)s_idx[r] * C + col4));
        ax += v.x; ay += v.y; az += v.z; aw += v.w;
    }

    float inv = ONE_MINUS_GAMMA / (float)cnt;
    float* dst = out + (size_t)c * C + col4;
    atomicAdd(dst + 0, ax * inv);
    atomicAdd(dst + 1, ay * inv);
    atomicAdd(dst + 2, az * inv);
    atomicAdd(dst + 3, aw * inv);
}

// ---------------------------------------------------------------------------
// Fallback path (general C): scalar scatter + single-CTA-per-class reduce.
// ---------------------------------------------------------------------------
__global__ __launch_bounds__(256) void k_scatter_s(const int* __restrict__ labels, int N) {
    int i = blockIdx.x * blockDim.x + threadIdx.x;
    if (i >= N) return;
    int b = labels[i] * KSUB + (i & (KSUB - 1));
    int p = atomicAdd(&g_cursor[b], 1);
    if (p < CAP) g_rowidx[b * CAP + p] = i;
}

__global__ __launch_bounds__(256) void k_reduce_s(
    const float* __restrict__ preds,
    const float* __restrict__ val_preds,
    float* __restrict__ out,
    int C)
{
    int c   = blockIdx.x;
    int tid = threadIdx.x;

    __shared__ int s_base[KSUB + 1];
    __shared__ int s_idx[SMAX];

    if (tid == 0) {
        int tot = 0;
        #pragma unroll
        for (int s = 0; s < KSUB; ++s) {
            s_base[s] = tot;
            int cs = g_cursor[c * KSUB + s];
            tot += (cs < CAP ? cs : CAP);
        }
        s_base[KSUB] = tot;
    }
    __syncthreads();
    #pragma unroll
    for (int s = 0; s < KSUB; ++s) {
        int lo = s_base[s], cs = s_base[s + 1] - lo;
        const int* src = &g_rowidx[(c * KSUB + s) * CAP];
        for (int j = tid; j < cs; j += 256) s_idx[lo + j] = src[j];
    }
    __syncthreads();
    if (tid < KSUB) g_cursor[c * KSUB + tid] = 0;

    int cnt = s_base[KSUB];
    for (int col = tid; col < C; col += 256) {
        float acc = 0.f;
        for (int r = 0; r < cnt; ++r)
            acc += __ldcs(preds + (size_t)s_idx[r] * C + col);
        float vp = val_preds[(size_t)c * C + col];
        out[(size_t)c * C + col] =
            (cnt > 0) ? (ONE_MINUS_GAMMA * acc / (float)cnt + GAMMA * vp) : vp;
    }
}

extern "C" void kernel_launch(void* const* d_in, const int* in_sizes, int n_in,
                              void* d_out, int out_size) {
    const float* preds     = (const float*)d_in[0];
    const int*   labels    = (const int*)  d_in[1];
    const float* val_preds = (const float*)d_in[2];
    float*       out       = (float*)d_out;

    const int N = in_sizes[1];       // 131072
    const int C = in_sizes[0] / N;   // 1000

    if ((C % 4) == 0 && C <= C_MAX) {
        int tot4 = (C * C) >> 2;     // C*C divisible by 4 when C%4==0
        k_scatter_init<<<512, 256>>>(labels, val_preds, out, N, tot4);
        k_partial_v4<<<2 * C, 256>>>(preds, val_preds, out, C);
    } else {
        k_scatter_s<<<(N + 255) / 256, 256>>>(labels, N);
        k_reduce_s<<<C, 256>>>(preds, val_preds, out, C);
    }
}

// round 13
// speedup vs baseline: 1.0441x; 1.0441x over previous
#include <cuda_runtime.h>
#include <cuda_bf16.h>

// ValScores: per-class mean of preds rows (segment reduction by label) + EMA.
//   out[c,:] = cnt[c]>0 ? 0.1*mean_c(preds) + 0.9*val_preds[c,:] : val_preds[c,:]
//
// FINAL: exact reproduction of the session-best configuration (R2, 94.7us;
// reduce 89.2us @ DRAM 76%), plus __launch_bounds__(256,8) insurance so ptxas
// can never exceed the 32-reg / 8-CTA-per-SM / single-wave budget (the silent
// failure mode of R6/R9).
//
// Complete experiment matrix (12 rounds):
//   R2  KSUB=8 bucket scatter + 1 CTA/class whole-row reduce      94.7  BEST
//   R7/R10 KSUB=16 variants                                       96.4-96.8
//   R11/R12 REDG row-split combine                                96.8-97.0
//   R3 ticket stealing (single-address atomic serialization)      116
//   R4 column split (DRAM locality 76%->54%)                      119
//   R5 row split + spin exchange                                  99
//   R6 8-row unroll (reg-starved, MLP collapsed)                  119
//   R8 fused + grid barrier (single-address spin)                 101
//   R9 shfl scan (regs 32->40 -> two waves)                       105
// Invariants: whole contiguous 4000B rows per CTA; 32 regs; one wave;
// zero cross-CTA coordination in the reduce.

#define C_MAX   1024
#define KSUB    8
#define CAP     256            // per sub-list capacity (expected ~16 +- 4)
#define SMAX    (KSUB * CAP)   // 2048 indices, 8KB smem
#define GAMMA   0.9f
#define ONE_MINUS_GAMMA 0.1f

__device__ int g_cursor[C_MAX * KSUB];        // zero-init at module load
__device__ int g_rowidx[C_MAX * KSUB * CAP];  // 8 MB scratch

// ---------------------------------------------------------------------------
// Scatter: each thread handles 4 consecutive elements via one int4 label load.
// Sub-cursor chosen from the element index low bits -> adjacent elements of
// the same class hit different L2 lines.
// ---------------------------------------------------------------------------
__global__ __launch_bounds__(256) void k_scatter_v4(const int4* __restrict__ labels4, int n4) {
    int t = blockIdx.x * blockDim.x + threadIdx.x;
    if (t >= n4) return;
    int4 L = labels4[t];
    int i0 = t * 4;

    int s0 = (i0 + 0) & (KSUB - 1);
    int s1 = (i0 + 1) & (KSUB - 1);
    int s2 = (i0 + 2) & (KSUB - 1);
    int s3 = (i0 + 3) & (KSUB - 1);

    int b0 = L.x * KSUB + s0;
    int b1 = L.y * KSUB + s1;
    int b2 = L.z * KSUB + s2;
    int b3 = L.w * KSUB + s3;

    int p0 = atomicAdd(&g_cursor[b0], 1);
    int p1 = atomicAdd(&g_cursor[b1], 1);
    int p2 = atomicAdd(&g_cursor[b2], 1);
    int p3 = atomicAdd(&g_cursor[b3], 1);

    if (p0 < CAP) g_rowidx[b0 * CAP + p0] = i0 + 0;
    if (p1 < CAP) g_rowidx[b1 * CAP + p1] = i0 + 1;
    if (p2 < CAP) g_rowidx[b2 * CAP + p2] = i0 + 2;
    if (p3 < CAP) g_rowidx[b3 * CAP + p3] = i0 + 3;
}

// Scalar fallback for N % 4 != 0.
__global__ __launch_bounds__(256) void k_scatter_s(const int* __restrict__ labels, int N) {
    int i = blockIdx.x * blockDim.x + threadIdx.x;
    if (i >= N) return;
    int b = labels[i] * KSUB + (i & (KSUB - 1));
    int p = atomicAdd(&g_cursor[b], 1);
    if (p < CAP) g_rowidx[b * CAP + p] = i;
}

// ---------------------------------------------------------------------------
// Reduce: one CTA per class, 256 threads, pinned to 8 CTAs/SM (<=32 regs).
// Thread t owns cols [4t, 4t+3]. Hot path identical to the 94.7us winner.
// ---------------------------------------------------------------------------
__global__ __launch_bounds__(256, 8) void k_reduce_v4(
    const float* __restrict__ preds,
    const float* __restrict__ val_preds,
    float* __restrict__ out,
    int C)
{
    int c   = blockIdx.x;
    int tid = threadIdx.x;

    __shared__ int s_base[KSUB + 1];
    __shared__ int s_idx[SMAX];

    // Per-sub counts -> prefix (KSUB=8, done by thread 0; trivial).
    if (tid == 0) {
        int tot = 0;
        #pragma unroll
        for (int s = 0; s < KSUB; ++s) {
            s_base[s] = tot;
            int cs = g_cursor[c * KSUB + s];
            tot += (cs < CAP ? cs : CAP);
        }
        s_base[KSUB] = tot;
    }
    __syncthreads();

    // Cooperative stage of all row indices into smem (compacted).
    #pragma unroll
    for (int s = 0; s < KSUB; ++s) {
        int lo = s_base[s], cs = s_base[s + 1] - lo;
        const int* src = &g_rowidx[(c * KSUB + s) * CAP];
        for (int j = tid; j < cs; j += 256) s_idx[lo + j] = src[j];
    }
    __syncthreads();

    // Sole reader of this class's cursors -> reset for next graph replay.
    if (tid < KSUB) g_cursor[c * KSUB + tid] = 0;

    int cnt  = s_base[KSUB];
    int col4 = tid * 4;
    if (col4 >= C) return;

    float ax = 0.f, ay = 0.f, az = 0.f, aw = 0.f;
    int r = 0;
    // 4 independent 16B streaming loads in flight per thread
    // (the 32-register MLP maximum that preserves 8 CTAs/SM).
    for (; r + 3 < cnt; r += 4) {
        const float4* p0 = (const float4*)(preds + (size_t)s_idx[r + 0] * C + col4);
        const float4* p1 = (const float4*)(preds + (size_t)s_idx[r + 1] * C + col4);
        const float4* p2 = (const float4*)(preds + (size_t)s_idx[r + 2] * C + col4);
        const float4* p3 = (const float4*)(preds + (size_t)s_idx[r + 3] * C + col4);
        float4 v0 = __ldcs(p0);
        float4 v1 = __ldcs(p1);
        float4 v2 = __ldcs(p2);
        float4 v3 = __ldcs(p3);
        ax += v0.x; ay += v0.y; az += v0.z; aw += v0.w;
        ax += v1.x; ay += v1.y; az += v1.z; aw += v1.w;
        ax += v2.x; ay += v2.y; az += v2.z; aw += v2.w;
        ax += v3.x; ay += v3.y; az += v3.z; aw += v3.w;
    }
    for (; r < cnt; ++r) {
        float4 v = __ldcs((const float4*)(preds + (size_t)s_idx[r] * C + col4));
        ax += v.x; ay += v.y; az += v.z; aw += v.w;
    }

    float4 vp = *(const float4*)(val_preds + (size_t)c * C + col4);
    float4 o;
    if (cnt > 0) {
        float inv = ONE_MINUS_GAMMA / (float)cnt;
        o.x = ax * inv + GAMMA * vp.x;
        o.y = ay * inv + GAMMA * vp.y;
        o.z = az * inv + GAMMA * vp.z;
        o.w = aw * inv + GAMMA * vp.w;
    } else {
        o = vp;
    }
    *(float4*)(out + (size_t)c * C + col4) = o;
}

// Scalar-column fallback (C % 4 != 0 or C > 1024): 1 CTA per class.
__global__ __launch_bounds__(256) void k_reduce_s(
    const float* __restrict__ preds,
    const float* __restrict__ val_preds,
    float* __restrict__ out,
    int C)
{
    int c   = blockIdx.x;
    int tid = threadIdx.x;

    __shared__ int s_base[KSUB + 1];
    __shared__ int s_idx[SMAX];

    if (tid == 0) {
        int tot = 0;
        #pragma unroll
        for (int s = 0; s < KSUB; ++s) {
            s_base[s] = tot;
            int cs = g_cursor[c * KSUB + s];
            tot += (cs < CAP ? cs : CAP);
        }
        s_base[KSUB] = tot;
    }
    __syncthreads();
    #pragma unroll
    for (int s = 0; s < KSUB; ++s) {
        int lo = s_base[s], cs = s_base[s + 1] - lo;
        const int* src = &g_rowidx[(c * KSUB + s) * CAP];
        for (int j = tid; j < cs; j += 256) s_idx[lo + j] = src[j];
    }
    __syncthreads();
    if (tid < KSUB) g_cursor[c * KSUB + tid] = 0;

    int cnt = s_base[KSUB];
    for (int col = tid; col < C; col += 256) {
        float acc = 0.f;
        for (int r = 0; r < cnt; ++r)
            acc += __ldcs(preds + (size_t)s_idx[r] * C + col);
        float vp = val_preds[(size_t)c * C + col];
        out[(size_t)c * C + col] =
            (cnt > 0) ? (ONE_MINUS_GAMMA * acc / (float)cnt + GAMMA * vp) : vp;
    }
}

extern "C" void kernel_launch(void* const* d_in, const int* in_sizes, int n_in,
                              void* d_out, int out_size) {
    const float* preds     = (const float*)d_in[0];
    const int*   labels    = (const int*)  d_in[1];
    const float* val_preds = (const float*)d_in[2];
    float*       out       = (float*)d_out;

    const int N = in_sizes[1];       // 131072
    const int C = in_sizes[0] / N;   // 1000

    if ((N & 3) == 0) {
        int n4 = N / 4;
        k_scatter_v4<<<(n4 + 255) / 256, 256>>>((const int4*)labels, n4);
    } else {
        k_scatter_s<<<(N + 255) / 256, 256>>>(labels, N);
    }

    if ((C % 4) == 0 && C <= C_MAX) {
        k_reduce_v4<<<C, 256>>>(preds, val_preds, out, C);
    } else {
        k_reduce_s<<<C, 256>>>(preds, val_preds, out, C);
    }
}